// round 3
// baseline (speedup 1.0000x reference)
#include <cuda_runtime.h>
#include <cuda_bf16.h>

// Problem constants
#define NB   1024   // batch
#define NT   256    // time steps
#define ND   64     // embedding dim
#define NH   128    // hidden dim
#define N2H  256    // 2*H

// Scratch: precomputed input contributions (zero-init at module load; entries
// beyond seq_len are never read with effect — masked rows discard results).
__device__ float g_Xg[(size_t)NB * NT * N2H];  // 256 MB
__device__ float g_Xc[(size_t)NB * NT * NH];   // 128 MB

// ---------------------------------------------------------------------------
// Kernel 1: precompute Xg = x @ Wxg + gate_bias, Xc = x @ Wxc + cand_bias
// One block per batch row b; loops t in chunks of 8, skipping t >= seq_len.
// Shared: Wxg (64x256), Wxc (64x128), x stage (8x64).
// ---------------------------------------------------------------------------
__global__ __launch_bounds__(256, 1)
void precompute_kernel(const int* __restrict__ item_his,
                       const int* __restrict__ seq_lens,
                       const float* __restrict__ embedding,
                       const float* __restrict__ gate_kernel,
                       const float* __restrict__ gate_bias,
                       const float* __restrict__ cand_kernel,
                       const float* __restrict__ cand_bias) {
    extern __shared__ float sm[];
    float* Wxg = sm;                    // 64*256 = 16384 floats
    float* Wxc = Wxg + 64 * N2H;        // 64*128 = 8192
    float* xs  = Wxc + 64 * NH;         // 8*64   = 512

    const int tid = threadIdx.x;
    const int b   = blockIdx.x;
    const int len = seq_lens[b];

    // Wxg = gate_kernel rows [0,64) (contiguous); Wxc = cand_kernel rows [0,64)
    for (int i = tid; i < (64 * N2H) / 4; i += 256)
        ((float4*)Wxg)[i] = ((const float4*)gate_kernel)[i];
    for (int i = tid; i < (64 * NH) / 4; i += 256)
        ((float4*)Wxc)[i] = ((const float4*)cand_kernel)[i];
    __syncthreads();

    if (len <= 0) return;

    const float gb = gate_bias[tid];
    const int   cc = tid & 127;
    const int   r0 = (tid >> 7) * 4;
    const float cb = cand_bias[cc];

    for (int t0 = 0; t0 < len; t0 += 8) {
        // Gather 8 x-rows: thread -> (row tid/32, float2 at 2*(tid%32))
        {
            int j = tid >> 5;
            int e = (tid & 31) * 2;
            int t = t0 + j;
            float2 v = make_float2(0.f, 0.f);
            if (t < len) {
                int idx = item_his[b * NT + t];
                v = *(const float2*)&embedding[(size_t)idx * ND + e];
            }
            *(float2*)&xs[j * ND + e] = v;
        }
        __syncthreads();

        const float4* xs4 = (const float4*)xs;

        // Xg: thread == column (0..255), 8 rows
        float acc[8];
        #pragma unroll
        for (int r = 0; r < 8; r++) acc[r] = 0.f;
        #pragma unroll 4
        for (int k4 = 0; k4 < 16; k4++) {
            float w0 = Wxg[(4 * k4 + 0) * N2H + tid];
            float w1 = Wxg[(4 * k4 + 1) * N2H + tid];
            float w2 = Wxg[(4 * k4 + 2) * N2H + tid];
            float w3 = Wxg[(4 * k4 + 3) * N2H + tid];
            #pragma unroll
            for (int r = 0; r < 8; r++) {
                float4 hv = xs4[r * 16 + k4];  // broadcast
                acc[r] += hv.x * w0 + hv.y * w1 + hv.z * w2 + hv.w * w3;
            }
        }
        #pragma unroll
        for (int r = 0; r < 8; r++) {
            int t = t0 + r;
            if (t < len)
                g_Xg[((size_t)b * NT + t) * N2H + tid] = acc[r] + gb;
        }

        // Xc: column = tid&127, rows r0..r0+3
        float acc2[4];
        #pragma unroll
        for (int r = 0; r < 4; r++) acc2[r] = 0.f;
        #pragma unroll 4
        for (int k4 = 0; k4 < 16; k4++) {
            float w0 = Wxc[(4 * k4 + 0) * NH + cc];
            float w1 = Wxc[(4 * k4 + 1) * NH + cc];
            float w2 = Wxc[(4 * k4 + 2) * NH + cc];
            float w3 = Wxc[(4 * k4 + 3) * NH + cc];
            #pragma unroll
            for (int r = 0; r < 4; r++) {
                float4 hv = xs4[(r0 + r) * 16 + k4];  // broadcast
                acc2[r] += hv.x * w0 + hv.y * w1 + hv.z * w2 + hv.w * w3;
            }
        }
        #pragma unroll
        for (int r = 0; r < 4; r++) {
            int t = t0 + r0 + r;
            if (t < len)
                g_Xc[((size_t)b * NT + t) * NH + cc] = acc2[r] + cb;
        }
        __syncthreads();  // xs reused next chunk
    }
}

// ---------------------------------------------------------------------------
// Kernel 2: recurrence. 128 blocks x 8 batch rows, 256 threads.
// Shared: Whg (128x256, 128KB), Whc (128x128, 64KB), h/rh/ru staging.
// ---------------------------------------------------------------------------
__global__ __launch_bounds__(256, 1)
void gru_kernel(const int* __restrict__ seq_lens,
                const float* __restrict__ gate_kernel,
                const float* __restrict__ cand_kernel,
                float* __restrict__ out) {
    extern __shared__ float sm[];
    float* Whg = sm;                     // 128*256 = 32768 floats
    float* Whc = Whg + NH * N2H;         // 128*128 = 16384
    float* hs  = Whc + NH * NH;          // 8*128   = 1024
    float* rh  = hs + 8 * NH;            // 8*128   = 1024
    float* ru  = rh + 8 * NH;            // 8*256   = 2048
    __shared__ int s_len[8];
    __shared__ int s_maxlen;

    const int tid = threadIdx.x;

    // Hidden-weight slices are contiguous (rows [64,192) of each kernel)
    const float4* Whg_g = (const float4*)(gate_kernel + 64 * N2H);
    const float4* Whc_g = (const float4*)(cand_kernel + 64 * NH);
    for (int i = tid; i < (NH * N2H) / 4; i += 256) ((float4*)Whg)[i] = Whg_g[i];
    for (int i = tid; i < (NH * NH) / 4;  i += 256) ((float4*)Whc)[i] = Whc_g[i];
    for (int i = tid; i < 8 * NH; i += 256) hs[i] = 0.f;
    if (tid < 8) s_len[tid] = seq_lens[blockIdx.x * 8 + tid];
    __syncthreads();
    if (tid == 0) {
        int m = 0;
        #pragma unroll
        for (int j = 0; j < 8; j++) m = max(m, s_len[j]);
        s_maxlen = m;
    }
    __syncthreads();
    const int maxlen = s_maxlen;

    const int cc = tid & 127;
    const int r0 = (tid >> 7) * 4;

    for (int t = 0; t < maxlen; t++) {
        // ---- Phase A: gates = sigmoid(h @ Whg + Xg) ; thread == gate column
        float acc[8];
        #pragma unroll
        for (int r = 0; r < 8; r++) acc[r] = 0.f;
        const float4* h4 = (const float4*)hs;
        #pragma unroll 4
        for (int k4 = 0; k4 < 32; k4++) {
            float w0 = Whg[(4 * k4 + 0) * N2H + tid];
            float w1 = Whg[(4 * k4 + 1) * N2H + tid];
            float w2 = Whg[(4 * k4 + 2) * N2H + tid];
            float w3 = Whg[(4 * k4 + 3) * N2H + tid];
            #pragma unroll
            for (int r = 0; r < 8; r++) {
                float4 hv = h4[r * 32 + k4];  // broadcast
                acc[r] += hv.x * w0 + hv.y * w1 + hv.z * w2 + hv.w * w3;
            }
        }
        #pragma unroll
        for (int r = 0; r < 8; r++) {
            size_t row = (size_t)(blockIdx.x * 8 + r) * NT + t;
            float pre = acc[r] + g_Xg[row * N2H + tid];
            ru[r * N2H + tid] = 1.f / (1.f + __expf(-pre));
        }
        __syncthreads();

        // ---- Phase B: rh = r * h   (r = ru cols [0,128))
        #pragma unroll
        for (int i = tid; i < 8 * NH; i += 256) {
            int r = i >> 7, k = i & 127;
            rh[i] = ru[r * N2H + k] * hs[i];
        }
        __syncthreads();

        // ---- Phase C: c = tanh(rh @ Whc + Xc); h = u*h + (1-u)*c (masked)
        float acc2[4];
        #pragma unroll
        for (int r = 0; r < 4; r++) acc2[r] = 0.f;
        const float4* rh4 = (const float4*)rh;
        #pragma unroll 4
        for (int k4 = 0; k4 < 32; k4++) {
            float w0 = Whc[(4 * k4 + 0) * NH + cc];
            float w1 = Whc[(4 * k4 + 1) * NH + cc];
            float w2 = Whc[(4 * k4 + 2) * NH + cc];
            float w3 = Whc[(4 * k4 + 3) * NH + cc];
            #pragma unroll
            for (int r = 0; r < 4; r++) {
                float4 hv = rh4[(r0 + r) * 32 + k4];  // broadcast
                acc2[r] += hv.x * w0 + hv.y * w1 + hv.z * w2 + hv.w * w3;
            }
        }
        #pragma unroll
        for (int rr = 0; rr < 4; rr++) {
            int r = r0 + rr;
            if (t < s_len[r]) {
                size_t row = (size_t)(blockIdx.x * 8 + r) * NT + t;
                float pre = acc2[rr] + g_Xc[row * NH + cc];
                float cnd = tanhf(pre);
                float u   = ru[r * N2H + NH + cc];
                float h   = hs[r * NH + cc];
                hs[r * NH + cc] = u * h + (1.f - u) * cnd;
            }
        }
        __syncthreads();
    }

    for (int i = tid; i < 8 * NH; i += 256)
        out[blockIdx.x * (8 * NH) + i] = hs[i];
}

// ---------------------------------------------------------------------------
extern "C" void kernel_launch(void* const* d_in, const int* in_sizes, int n_in,
                              void* d_out, int out_size) {
    const int*   item_his    = (const int*)d_in[0];
    const int*   seq_lens    = (const int*)d_in[1];
    const float* embedding   = (const float*)d_in[2];
    const float* gate_kernel = (const float*)d_in[3];
    const float* gate_bias   = (const float*)d_in[4];
    const float* cand_kernel = (const float*)d_in[5];
    const float* cand_bias   = (const float*)d_in[6];
    float* out = (float*)d_out;

    const int smem1 = (64 * N2H + 64 * NH + 8 * ND) * sizeof(float);        // ~98 KB
    const int smem2 = (NH * N2H + NH * NH + 8 * NH * 2 + 8 * N2H) * sizeof(float);  // ~208 KB

    static bool attr_set = false;
    if (!attr_set) {
        cudaFuncSetAttribute(precompute_kernel,
                             cudaFuncAttributeMaxDynamicSharedMemorySize, smem1);
        cudaFuncSetAttribute(gru_kernel,
                             cudaFuncAttributeMaxDynamicSharedMemorySize, smem2);
        attr_set = true;
    }

    precompute_kernel<<<NB, 256, smem1>>>(item_his, seq_lens, embedding,
                                          gate_kernel, gate_bias,
                                          cand_kernel, cand_bias);
    gru_kernel<<<NB / 8, 256, smem2>>>(seq_lens, gate_kernel, cand_kernel, out);
}

// round 4
// speedup vs baseline: 2.1247x; 2.1247x over previous
#include <cuda_runtime.h>
#include <cuda_bf16.h>

// Problem constants
#define NB   1024   // batch
#define NT   256    // time steps
#define ND   64     // embedding dim
#define NH   128    // hidden dim
#define N2H  256    // 2*H
#define RPB  4      // rows per gru block
#define NBLK (NB / RPB)

// Scratch (device globals; persist across graph replays but rewritten
// deterministically each launch; never-written tail cells stay 0 and are
// masked out of the h update anyway).
__device__ float g_Xg[(size_t)NB * NT * N2H];  // 256 MB
__device__ float g_Xc[(size_t)NB * NT * NH];   // 128 MB
__device__ int   g_hist[256];
__device__ int   g_off[256];
__device__ int   g_perm[NB];

// ---------------------------------------------------------------------------
// Counting sort of batch rows by seq_len, DESCENDING (LPT block scheduling).
// ---------------------------------------------------------------------------
__global__ void sort_zero_kernel() {
    if (threadIdx.x < 256) g_hist[threadIdx.x] = 0;
}
__global__ void sort_hist_kernel(const int* __restrict__ lens) {
    int b = blockIdx.x * 256 + threadIdx.x;
    if (b < NB) {
        int l = min(max(lens[b], 0), 255);
        atomicAdd(&g_hist[l], 1);
    }
}
__global__ void sort_scan_kernel() {
    if (threadIdx.x == 0 && blockIdx.x == 0) {
        int run = 0;
        for (int l = 255; l >= 0; --l) { g_off[l] = run; run += g_hist[l]; }
    }
}
__global__ void sort_scatter_kernel(const int* __restrict__ lens) {
    int b = blockIdx.x * 256 + threadIdx.x;
    if (b < NB) {
        int l = min(max(lens[b], 0), 255);
        int p = atomicAdd(&g_off[l], 1);
        g_perm[p] = b;
    }
}

// ---------------------------------------------------------------------------
// Kernel 1: precompute Xg = x @ Wxg + gate_bias, Xc = x @ Wxc + cand_bias
// One block per batch row b; loops t in chunks of 8, skipping t >= seq_len.
// ---------------------------------------------------------------------------
__global__ __launch_bounds__(256, 1)
void precompute_kernel(const int* __restrict__ item_his,
                       const int* __restrict__ seq_lens,
                       const float* __restrict__ embedding,
                       const float* __restrict__ gate_kernel,
                       const float* __restrict__ gate_bias,
                       const float* __restrict__ cand_kernel,
                       const float* __restrict__ cand_bias) {
    extern __shared__ float sm[];
    float* Wxg = sm;                    // 64*256
    float* Wxc = Wxg + 64 * N2H;        // 64*128
    float* xs  = Wxc + 64 * NH;         // 8*64

    const int tid = threadIdx.x;
    const int b   = blockIdx.x;
    const int len = seq_lens[b];

    for (int i = tid; i < (64 * N2H) / 4; i += 256)
        ((float4*)Wxg)[i] = ((const float4*)gate_kernel)[i];
    for (int i = tid; i < (64 * NH) / 4; i += 256)
        ((float4*)Wxc)[i] = ((const float4*)cand_kernel)[i];
    __syncthreads();

    if (len <= 0) return;

    const float gb = gate_bias[tid];
    const int   cc = tid & 127;
    const int   r0 = (tid >> 7) * 4;
    const float cb = cand_bias[cc];

    for (int t0 = 0; t0 < len; t0 += 8) {
        {
            int j = tid >> 5;
            int e = (tid & 31) * 2;
            int t = t0 + j;
            float2 v = make_float2(0.f, 0.f);
            if (t < len) {
                int idx = item_his[b * NT + t];
                v = *(const float2*)&embedding[(size_t)idx * ND + e];
            }
            *(float2*)&xs[j * ND + e] = v;
        }
        __syncthreads();

        const float4* xs4 = (const float4*)xs;

        float acc[8];
        #pragma unroll
        for (int r = 0; r < 8; r++) acc[r] = 0.f;
        #pragma unroll 4
        for (int k4 = 0; k4 < 16; k4++) {
            float w0 = Wxg[(4 * k4 + 0) * N2H + tid];
            float w1 = Wxg[(4 * k4 + 1) * N2H + tid];
            float w2 = Wxg[(4 * k4 + 2) * N2H + tid];
            float w3 = Wxg[(4 * k4 + 3) * N2H + tid];
            #pragma unroll
            for (int r = 0; r < 8; r++) {
                float4 hv = xs4[r * 16 + k4];
                acc[r] += hv.x * w0 + hv.y * w1 + hv.z * w2 + hv.w * w3;
            }
        }
        #pragma unroll
        for (int r = 0; r < 8; r++) {
            int t = t0 + r;
            if (t < len)
                g_Xg[((size_t)b * NT + t) * N2H + tid] = acc[r] + gb;
        }

        float acc2[4];
        #pragma unroll
        for (int r = 0; r < 4; r++) acc2[r] = 0.f;
        #pragma unroll 4
        for (int k4 = 0; k4 < 16; k4++) {
            float w0 = Wxc[(4 * k4 + 0) * NH + cc];
            float w1 = Wxc[(4 * k4 + 1) * NH + cc];
            float w2 = Wxc[(4 * k4 + 2) * NH + cc];
            float w3 = Wxc[(4 * k4 + 3) * NH + cc];
            #pragma unroll
            for (int r = 0; r < 4; r++) {
                float4 hv = xs4[(r0 + r) * 16 + k4];
                acc2[r] += hv.x * w0 + hv.y * w1 + hv.z * w2 + hv.w * w3;
            }
        }
        #pragma unroll
        for (int r = 0; r < 4; r++) {
            int t = t0 + r0 + r;
            if (t < len)
                g_Xc[((size_t)b * NT + t) * NH + cc] = acc2[r] + cb;
        }
        __syncthreads();
    }
}

// ---------------------------------------------------------------------------
// Kernel 2: recurrence. 256 blocks x 4 sorted rows, 512 threads.
// Shared: Whg (128x256), Whc (128x128), h/rh/ru staging. 2 barriers/step.
// ---------------------------------------------------------------------------
__global__ __launch_bounds__(512, 1)
void gru_kernel(const int* __restrict__ seq_lens,
                const float* __restrict__ gate_kernel,
                const float* __restrict__ cand_kernel,
                float* __restrict__ out) {
    extern __shared__ float sm[];
    float* Whg = sm;                     // 32768 floats
    float* Whc = Whg + NH * N2H;         // 16384
    float* hs  = Whc + NH * NH;          // RPB*128 = 512
    float* rh  = hs + RPB * NH;          // 512
    float* ru  = rh + RPB * NH;          // RPB*256 = 1024
    __shared__ int s_len[RPB];
    __shared__ int s_ob[RPB];
    __shared__ int s_maxlen;

    const int tid = threadIdx.x;

    const float4* Whg_g = (const float4*)(gate_kernel + 64 * N2H);
    const float4* Whc_g = (const float4*)(cand_kernel + 64 * NH);
    for (int i = tid; i < (NH * N2H) / 4; i += 512) ((float4*)Whg)[i] = Whg_g[i];
    for (int i = tid; i < (NH * NH) / 4;  i += 512) ((float4*)Whc)[i] = Whc_g[i];
    for (int i = tid; i < RPB * NH; i += 512) hs[i] = 0.f;
    if (tid < RPB) {
        int ob = g_perm[blockIdx.x * RPB + tid];
        s_ob[tid] = ob;
        s_len[tid] = seq_lens[ob];
    }
    __syncthreads();
    if (tid == 0) {
        int m = 0;
        #pragma unroll
        for (int j = 0; j < RPB; j++) m = max(m, s_len[j]);
        s_maxlen = m;
    }
    __syncthreads();
    const int maxlen = s_maxlen;

    // Phase A mapping: gate column c (0..255), row pair {2g, 2g+1}
    const int c  = tid & 255;
    const int gA = tid >> 8;
    const int rA0 = 2 * gA, rA1 = 2 * gA + 1;
    // Phase C mapping: cand column cc (0..127), row q (0..3)
    const int cc = tid & 127;
    const int q  = tid >> 7;

    const float* xg0 = g_Xg + ((size_t)s_ob[rA0] * NT) * N2H + c;
    const float* xg1 = g_Xg + ((size_t)s_ob[rA1] * NT) * N2H + c;
    const float* xcb = g_Xc + ((size_t)s_ob[q]  * NT) * NH  + cc;
    const int mylen = s_len[q];

    for (int t = 0; t < maxlen; t++) {
        // Prefetch input contributions (hide DRAM/L2 latency under FMA loop)
        const float xgv0 = xg0[(size_t)t * N2H];
        const float xgv1 = xg1[(size_t)t * N2H];
        const float xcv  = xcb[(size_t)t * NH];

        // ---- Phase A: gates = sigmoid(h @ Whg + Xg), fused rh = r*h
        float a00 = 0.f, a01 = 0.f, a10 = 0.f, a11 = 0.f;
        const float4* h4 = (const float4*)hs;
        #pragma unroll 4
        for (int k4 = 0; k4 < 32; k4++) {
            float w0 = Whg[(4 * k4 + 0) * N2H + c];
            float w1 = Whg[(4 * k4 + 1) * N2H + c];
            float w2 = Whg[(4 * k4 + 2) * N2H + c];
            float w3 = Whg[(4 * k4 + 3) * N2H + c];
            float4 h0 = h4[rA0 * 32 + k4];  // broadcast
            float4 h1 = h4[rA1 * 32 + k4];  // broadcast
            a00 += h0.x * w0; a00 += h0.z * w2;
            a01 += h0.y * w1; a01 += h0.w * w3;
            a10 += h1.x * w0; a10 += h1.z * w2;
            a11 += h1.y * w1; a11 += h1.w * w3;
        }
        float pre0 = (a00 + a01) + xgv0;
        float pre1 = (a10 + a11) + xgv1;
        float gt0 = 1.f / (1.f + __expf(-pre0));
        float gt1 = 1.f / (1.f + __expf(-pre1));
        ru[rA0 * N2H + c] = gt0;
        ru[rA1 * N2H + c] = gt1;
        if (c < NH) {  // r-gate half computes rh directly (phase B merged)
            rh[rA0 * NH + c] = gt0 * hs[rA0 * NH + c];
            rh[rA1 * NH + c] = gt1 * hs[rA1 * NH + c];
        }
        __syncthreads();

        // ---- Phase C: c = tanh(rh @ Whc + Xc); h = u*h + (1-u)*c (masked)
        float b0 = 0.f, b1 = 0.f;
        const float4* rh4 = (const float4*)rh;
        #pragma unroll 4
        for (int k4 = 0; k4 < 32; k4++) {
            float w0 = Whc[(4 * k4 + 0) * NH + cc];
            float w1 = Whc[(4 * k4 + 1) * NH + cc];
            float w2 = Whc[(4 * k4 + 2) * NH + cc];
            float w3 = Whc[(4 * k4 + 3) * NH + cc];
            float4 hv = rh4[q * 32 + k4];  // broadcast
            b0 += hv.x * w0; b0 += hv.z * w2;
            b1 += hv.y * w1; b1 += hv.w * w3;
        }
        if (t < mylen) {
            float cnd = tanhf((b0 + b1) + xcv);
            float u   = ru[q * N2H + NH + cc];
            float h   = hs[q * NH + cc];
            hs[q * NH + cc] = u * h + (1.f - u) * cnd;
        }
        __syncthreads();
    }

    // Scatter final h back to original batch positions
    for (int i = tid; i < RPB * NH; i += 512) {
        int r = i >> 7, k = i & 127;
        out[s_ob[r] * NH + k] = hs[i];
    }
}

// ---------------------------------------------------------------------------
extern "C" void kernel_launch(void* const* d_in, const int* in_sizes, int n_in,
                              void* d_out, int out_size) {
    const int*   item_his    = (const int*)d_in[0];
    const int*   seq_lens    = (const int*)d_in[1];
    const float* embedding   = (const float*)d_in[2];
    const float* gate_kernel = (const float*)d_in[3];
    const float* gate_bias   = (const float*)d_in[4];
    const float* cand_kernel = (const float*)d_in[5];
    const float* cand_bias   = (const float*)d_in[6];
    float* out = (float*)d_out;

    const int smem1 = (64 * N2H + 64 * NH + 8 * ND) * sizeof(float);            // ~98 KB
    const int smem2 = (NH * N2H + NH * NH + RPB * NH * 2 + RPB * N2H) * sizeof(float);  // ~200 KB

    static bool attr_set = false;
    if (!attr_set) {
        cudaFuncSetAttribute(precompute_kernel,
                             cudaFuncAttributeMaxDynamicSharedMemorySize, smem1);
        cudaFuncSetAttribute(gru_kernel,
                             cudaFuncAttributeMaxDynamicSharedMemorySize, smem2);
        attr_set = true;
    }

    // Sort batch rows by length (descending) for balanced, low-waste blocks
    sort_zero_kernel<<<1, 256>>>();
    sort_hist_kernel<<<NB / 256, 256>>>(seq_lens);
    sort_scan_kernel<<<1, 32>>>();
    sort_scatter_kernel<<<NB / 256, 256>>>(seq_lens);

    precompute_kernel<<<NB, 256, smem1>>>(item_his, seq_lens, embedding,
                                          gate_kernel, gate_bias,
                                          cand_kernel, cand_bias);
    gru_kernel<<<NBLK, 512, smem2>>>(seq_lens, gate_kernel, cand_kernel, out);
}

// round 5
// speedup vs baseline: 2.5172x; 1.1848x over previous
#include <cuda_runtime.h>
#include <cstdint>

// Problem constants
#define NB   1024   // batch
#define NT   256    // time steps
#define ND   64     // embedding dim
#define NH   128    // hidden dim
#define N2H  256    // 2*H
#define RPB  4      // rows per gru block
#define NBLK (NB / RPB)
#define WST  132    // padded k-stride for transposed weights (132 % 8 == 4 -> conflict-free LDS.128)

// Scratch (device globals; rewritten deterministically each launch)
__device__ float g_Xg[(size_t)NB * NT * N2H];  // 256 MB
__device__ float g_Xc[(size_t)NB * NT * NH];   // 128 MB
__device__ int   g_perm[NB];

// ---------------------------------------------------------------------------
// packed f32x2 helpers (sm_100+): ptxas won't emit FFMA2 from C++, so PTX.
// ---------------------------------------------------------------------------
__device__ __forceinline__ uint64_t dup2(float w) {
    uint64_t r; uint32_t wi = __float_as_uint(w);
    asm("mov.b64 %0, {%1, %1};" : "=l"(r) : "r"(wi));
    return r;
}
__device__ __forceinline__ void fma2(uint64_t& d, uint64_t a, uint64_t b) {
    asm("fma.rn.f32x2 %0, %1, %2, %0;" : "+l"(d) : "l"(a), "l"(b));
}
__device__ __forceinline__ uint64_t add2(uint64_t a, uint64_t b) {
    uint64_t r; asm("add.rn.f32x2 %0, %1, %2;" : "=l"(r) : "l"(a), "l"(b));
    return r;
}
__device__ __forceinline__ float2 unpk(uint64_t v) {
    uint32_t lo, hi;
    asm("mov.b64 {%0, %1}, %2;" : "=r"(lo), "=r"(hi) : "l"(v));
    return make_float2(__uint_as_float(lo), __uint_as_float(hi));
}

// ---------------------------------------------------------------------------
// Single-launch counting sort of batch rows by seq_len, DESCENDING (LPT).
// One block, 1024 threads (== NB).
// ---------------------------------------------------------------------------
__global__ __launch_bounds__(NB, 1)
void sort_all_kernel(const int* __restrict__ lens) {
    __shared__ int hist[256];
    __shared__ int off[256];
    const int tid = threadIdx.x;
    if (tid < 256) hist[tid] = 0;
    __syncthreads();
    const int l = min(max(lens[tid], 0), 255);
    atomicAdd(&hist[l], 1);
    __syncthreads();
    if (tid == 0) {
        int run = 0;
        for (int i = 255; i >= 0; --i) { off[i] = run; run += hist[i]; }
    }
    __syncthreads();
    int p = atomicAdd(&off[l], 1);
    g_perm[p] = tid;
}

// ---------------------------------------------------------------------------
// Kernel 1: precompute Xg = x @ Wxg + gate_bias, Xc = x @ Wxc + cand_bias
// One block per batch row b; chunks of 8 timesteps, double-buffered gather.
// ---------------------------------------------------------------------------
__global__ __launch_bounds__(256, 2)
void precompute_kernel(const int* __restrict__ item_his,
                       const int* __restrict__ seq_lens,
                       const float* __restrict__ embedding,
                       const float* __restrict__ gate_kernel,
                       const float* __restrict__ gate_bias,
                       const float* __restrict__ cand_kernel,
                       const float* __restrict__ cand_bias) {
    extern __shared__ float sm[];
    float* Wxg = sm;                    // 64*256
    float* Wxc = Wxg + 64 * N2H;        // 64*128
    float* xs  = Wxc + 64 * NH;         // 8*64

    const int tid = threadIdx.x;
    const int b   = blockIdx.x;
    const int len = seq_lens[b];

    for (int i = tid; i < (64 * N2H) / 4; i += 256)
        ((float4*)Wxg)[i] = ((const float4*)gate_kernel)[i];
    for (int i = tid; i < (64 * NH) / 4; i += 256)
        ((float4*)Wxc)[i] = ((const float4*)cand_kernel)[i];
    __syncthreads();

    if (len <= 0) return;

    const float gb = gate_bias[tid];
    const int   cc = tid & 127;
    const int   r0 = (tid >> 7) * 4;
    const float cb = cand_bias[cc];

    const int j = tid >> 5;          // gather row 0..7
    const int e = (tid & 31) * 2;    // gather element pair

    // prefetch chunk 0
    float2 v = make_float2(0.f, 0.f);
    if (j < len) {
        int idx = item_his[b * NT + j];
        v = *(const float2*)&embedding[(size_t)idx * ND + e];
    }

    for (int t0 = 0; t0 < len; t0 += 8) {
        *(float2*)&xs[j * ND + e] = v;
        __syncthreads();

        // prefetch next chunk (overlaps with compute below)
        {
            int t = t0 + 8 + j;
            v = make_float2(0.f, 0.f);
            if (t < len) {
                int idx = item_his[b * NT + t];
                v = *(const float2*)&embedding[(size_t)idx * ND + e];
            }
        }

        const float4* xs4 = (const float4*)xs;

        float acc[8];
        #pragma unroll
        for (int r = 0; r < 8; r++) acc[r] = 0.f;
        #pragma unroll 4
        for (int k4 = 0; k4 < 16; k4++) {
            float w0 = Wxg[(4 * k4 + 0) * N2H + tid];
            float w1 = Wxg[(4 * k4 + 1) * N2H + tid];
            float w2 = Wxg[(4 * k4 + 2) * N2H + tid];
            float w3 = Wxg[(4 * k4 + 3) * N2H + tid];
            #pragma unroll
            for (int r = 0; r < 8; r++) {
                float4 hv = xs4[r * 16 + k4];
                acc[r] += hv.x * w0 + hv.y * w1 + hv.z * w2 + hv.w * w3;
            }
        }
        #pragma unroll
        for (int r = 0; r < 8; r++) {
            int t = t0 + r;
            if (t < len)
                g_Xg[((size_t)b * NT + t) * N2H + tid] = acc[r] + gb;
        }

        float acc2[4];
        #pragma unroll
        for (int r = 0; r < 4; r++) acc2[r] = 0.f;
        #pragma unroll 4
        for (int k4 = 0; k4 < 16; k4++) {
            float w0 = Wxc[(4 * k4 + 0) * NH + cc];
            float w1 = Wxc[(4 * k4 + 1) * NH + cc];
            float w2 = Wxc[(4 * k4 + 2) * NH + cc];
            float w3 = Wxc[(4 * k4 + 3) * NH + cc];
            #pragma unroll
            for (int r = 0; r < 4; r++) {
                float4 hv = xs4[(r0 + r) * 16 + k4];
                acc2[r] += hv.x * w0 + hv.y * w1 + hv.z * w2 + hv.w * w3;
            }
        }
        #pragma unroll
        for (int r = 0; r < 4; r++) {
            int t = t0 + r0 + r;
            if (t < len)
                g_Xc[((size_t)b * NT + t) * NH + cc] = acc2[r] + cb;
        }
        __syncthreads();
    }
}

// ---------------------------------------------------------------------------
// Kernel 2: recurrence. 256 blocks x 4 sorted rows, 512 threads.
// Transposed weights in smem (read ONCE per step), split-k x4, f32x2 FMA.
//   thread: sub = tid>>7 (k-quarter), cp = tid&127
//   Phase A: columns {cp, cp+128} of Whg; Phase C: column cp of Whc.
// ---------------------------------------------------------------------------
__global__ __launch_bounds__(512, 1)
void gru_kernel(const int* __restrict__ seq_lens,
                const float* __restrict__ gate_kernel,
                const float* __restrict__ cand_kernel,
                float* __restrict__ out) {
    extern __shared__ float sm[];
    float* WgT  = sm;                    // 256*132 = 33792 floats
    float* WcT  = WgT + 256 * WST;       // 128*132 = 16896
    float* hsT  = WcT + 128 * WST;       // 512  (hsT[k*4 + r])
    float* rhT  = hsT + 512;             // 512
    float* us   = rhT + 512;             // 512
    float* psA1 = us + 512;              // 3*128*4 = 1536 (r-gate partials)
    float* psA2 = psA1 + 1536;           // 1536 (u-gate partials)
    float* pcC  = psA2 + 1536;           // 1536 (cand partials)
    __shared__ int s_len[RPB];
    __shared__ int s_ob[RPB];
    __shared__ int s_maxlen;

    const int tid = threadIdx.x;

    // Build transposed weights: WgT[c*WST+k] = Whg[k][c], WcT[c*WST+k] = Whc[k][c]
    {
        const float4* Wg4 = (const float4*)(gate_kernel + 64 * N2H);  // [k][c], 64 f4/row
        for (int i = tid; i < (NH * N2H) / 4; i += 512) {
            int k = i >> 6, c4 = (i & 63) * 4;
            float4 w = Wg4[i];
            WgT[(c4 + 0) * WST + k] = w.x;
            WgT[(c4 + 1) * WST + k] = w.y;
            WgT[(c4 + 2) * WST + k] = w.z;
            WgT[(c4 + 3) * WST + k] = w.w;
        }
        const float4* Wc4 = (const float4*)(cand_kernel + 64 * NH);   // [k][c], 32 f4/row
        for (int i = tid; i < (NH * NH) / 4; i += 512) {
            int k = i >> 5, c4 = (i & 31) * 4;
            float4 w = Wc4[i];
            WcT[(c4 + 0) * WST + k] = w.x;
            WcT[(c4 + 1) * WST + k] = w.y;
            WcT[(c4 + 2) * WST + k] = w.z;
            WcT[(c4 + 3) * WST + k] = w.w;
        }
    }
    for (int i = tid; i < RPB * NH; i += 512) hsT[i] = 0.f;
    if (tid < RPB) {
        int ob = g_perm[blockIdx.x * RPB + tid];
        s_ob[tid] = ob;
        s_len[tid] = seq_lens[ob];
    }
    __syncthreads();
    if (tid == 0) {
        int m = 0;
        #pragma unroll
        for (int jj = 0; jj < RPB; jj++) m = max(m, s_len[jj]);
        s_maxlen = m;
    }
    __syncthreads();
    const int maxlen = s_maxlen;

    const int sub = tid >> 7;   // k-quarter 0..3
    const int cp  = tid & 127;  // column (A: cp & cp+128; C: cp)
    const int k0  = sub * 32;

    // Prefetch bases (used by sub==0 threads only)
    const float* xg0 = g_Xg + ((size_t)s_ob[0] * NT) * N2H + cp;
    const float* xg1 = g_Xg + ((size_t)s_ob[1] * NT) * N2H + cp;
    const float* xg2 = g_Xg + ((size_t)s_ob[2] * NT) * N2H + cp;
    const float* xg3 = g_Xg + ((size_t)s_ob[3] * NT) * N2H + cp;
    const float* xc0 = g_Xc + ((size_t)s_ob[0] * NT) * NH + cp;
    const float* xc1 = g_Xc + ((size_t)s_ob[1] * NT) * NH + cp;
    const float* xc2 = g_Xc + ((size_t)s_ob[2] * NT) * NH + cp;
    const float* xc3 = g_Xc + ((size_t)s_ob[3] * NT) * NH + cp;

    const float4*     wA0 = (const float4*)&WgT[cp * WST + k0];
    const float4*     wA1 = (const float4*)&WgT[(cp + 128) * WST + k0];
    const float4*     wC  = (const float4*)&WcT[cp * WST + k0];
    const ulonglong2* hp  = (const ulonglong2*)&hsT[k0 * 4];
    const ulonglong2* rp  = (const ulonglong2*)&rhT[k0 * 4];

    for (int t = 0; t < maxlen; t++) {
        // Prefetch input contributions (sub==0 threads; consumed after barrier)
        float xgr[4], xgu[4], xcv[4];
        if (sub == 0) {
            size_t og = (size_t)t * N2H, oc = (size_t)t * NH;
            xgr[0] = __ldg(xg0 + og); xgu[0] = __ldg(xg0 + og + NH); xcv[0] = __ldg(xc0 + oc);
            xgr[1] = __ldg(xg1 + og); xgu[1] = __ldg(xg1 + og + NH); xcv[1] = __ldg(xc1 + oc);
            xgr[2] = __ldg(xg2 + og); xgu[2] = __ldg(xg2 + og + NH); xcv[2] = __ldg(xc2 + oc);
            xgr[3] = __ldg(xg3 + og); xgu[3] = __ldg(xg3 + og + NH); xcv[3] = __ldg(xc3 + oc);
        }

        // ---- Phase A main: partial h @ Whg for k in [k0, k0+32)
        uint64_t a00 = 0, a01 = 0, a10 = 0, a11 = 0;  // (colR:r01,r23),(colU:r01,r23)
        #pragma unroll
        for (int i = 0; i < 8; i++) {
            float4 w0 = wA0[i];
            float4 w1 = wA1[i];
            ulonglong2 hA = hp[4 * i + 0];
            ulonglong2 hB = hp[4 * i + 1];
            ulonglong2 hC = hp[4 * i + 2];
            ulonglong2 hD = hp[4 * i + 3];
            uint64_t d, e;
            d = dup2(w0.x); e = dup2(w1.x);
            fma2(a00, hA.x, d); fma2(a01, hA.y, d); fma2(a10, hA.x, e); fma2(a11, hA.y, e);
            d = dup2(w0.y); e = dup2(w1.y);
            fma2(a00, hB.x, d); fma2(a01, hB.y, d); fma2(a10, hB.x, e); fma2(a11, hB.y, e);
            d = dup2(w0.z); e = dup2(w1.z);
            fma2(a00, hC.x, d); fma2(a01, hC.y, d); fma2(a10, hC.x, e); fma2(a11, hC.y, e);
            d = dup2(w0.w); e = dup2(w1.w);
            fma2(a00, hD.x, d); fma2(a01, hD.y, d); fma2(a10, hD.x, e); fma2(a11, hD.y, e);
        }
        if (sub != 0) {
            ulonglong2 v1; v1.x = a00; v1.y = a01;
            ulonglong2 v2; v2.x = a10; v2.y = a11;
            *(ulonglong2*)&psA1[((sub - 1) * 128 + cp) * 4] = v1;
            *(ulonglong2*)&psA2[((sub - 1) * 128 + cp) * 4] = v2;
        }
        __syncthreads();

        // ---- Phase A epilogue (sub==0): reduce, sigmoid, build rhT & us
        if (sub == 0) {
            #pragma unroll
            for (int jj = 0; jj < 3; jj++) {
                ulonglong2 v1 = *(const ulonglong2*)&psA1[(jj * 128 + cp) * 4];
                ulonglong2 v2 = *(const ulonglong2*)&psA2[(jj * 128 + cp) * 4];
                a00 = add2(a00, v1.x); a01 = add2(a01, v1.y);
                a10 = add2(a10, v2.x); a11 = add2(a11, v2.y);
            }
            float2 r01 = unpk(a00), r23 = unpk(a01);
            float2 u01 = unpk(a10), u23 = unpk(a11);
            float rg[4] = {r01.x, r01.y, r23.x, r23.y};
            float ug[4] = {u01.x, u01.y, u23.x, u23.y};
            float4 hv = *(const float4*)&hsT[cp * 4];
            float hh[4] = {hv.x, hv.y, hv.z, hv.w};
            float rh4[4], uu4[4];
            #pragma unroll
            for (int r = 0; r < 4; r++) {
                float gr = 1.f / (1.f + __expf(-(rg[r] + xgr[r])));
                float gu = 1.f / (1.f + __expf(-(ug[r] + xgu[r])));
                rh4[r] = gr * hh[r];
                uu4[r] = gu;
            }
            *(float4*)&rhT[cp * 4] = make_float4(rh4[0], rh4[1], rh4[2], rh4[3]);
            *(float4*)&us[cp * 4]  = make_float4(uu4[0], uu4[1], uu4[2], uu4[3]);
        }
        __syncthreads();

        // ---- Phase C main: partial rh @ Whc for k in [k0, k0+32)
        uint64_t b0 = 0, b1 = 0;
        #pragma unroll
        for (int i = 0; i < 8; i++) {
            float4 w = wC[i];
            ulonglong2 hA = rp[4 * i + 0];
            ulonglong2 hB = rp[4 * i + 1];
            ulonglong2 hC = rp[4 * i + 2];
            ulonglong2 hD = rp[4 * i + 3];
            uint64_t d;
            d = dup2(w.x); fma2(b0, hA.x, d); fma2(b1, hA.y, d);
            d = dup2(w.y); fma2(b0, hB.x, d); fma2(b1, hB.y, d);
            d = dup2(w.z); fma2(b0, hC.x, d); fma2(b1, hC.y, d);
            d = dup2(w.w); fma2(b0, hD.x, d); fma2(b1, hD.y, d);
        }
        if (sub != 0) {
            ulonglong2 v; v.x = b0; v.y = b1;
            *(ulonglong2*)&pcC[((sub - 1) * 128 + cp) * 4] = v;
        }
        __syncthreads();

        // ---- Phase C epilogue (sub==0): reduce, tanh, masked h update
        if (sub == 0) {
            #pragma unroll
            for (int jj = 0; jj < 3; jj++) {
                ulonglong2 v = *(const ulonglong2*)&pcC[(jj * 128 + cp) * 4];
                b0 = add2(b0, v.x); b1 = add2(b1, v.y);
            }
            float2 c01 = unpk(b0), c23 = unpk(b1);
            float cs[4] = {c01.x, c01.y, c23.x, c23.y};
            float4 hv = *(const float4*)&hsT[cp * 4];
            float4 uv = *(const float4*)&us[cp * 4];
            float hh[4] = {hv.x, hv.y, hv.z, hv.w};
            float uu[4] = {uv.x, uv.y, uv.z, uv.w};
            float hn[4];
            #pragma unroll
            for (int r = 0; r < 4; r++) {
                float cnd = tanhf(cs[r] + xcv[r]);
                float h2  = uu[r] * hh[r] + (1.f - uu[r]) * cnd;
                hn[r] = (t < s_len[r]) ? h2 : hh[r];
            }
            *(float4*)&hsT[cp * 4] = make_float4(hn[0], hn[1], hn[2], hn[3]);
        }
        __syncthreads();
    }

    // Scatter final h to original batch positions: hsT[k*4+r] = h[r][k]
    for (int i = tid; i < RPB * NH; i += 512) {
        int k = i >> 2, r = i & 3;
        out[s_ob[r] * NH + k] = hsT[i];
    }
}

// ---------------------------------------------------------------------------
extern "C" void kernel_launch(void* const* d_in, const int* in_sizes, int n_in,
                              void* d_out, int out_size) {
    const int*   item_his    = (const int*)d_in[0];
    const int*   seq_lens    = (const int*)d_in[1];
    const float* embedding   = (const float*)d_in[2];
    const float* gate_kernel = (const float*)d_in[3];
    const float* gate_bias   = (const float*)d_in[4];
    const float* cand_kernel = (const float*)d_in[5];
    const float* cand_bias   = (const float*)d_in[6];
    float* out = (float*)d_out;

    const int smem1 = (64 * N2H + 64 * NH + 8 * ND) * sizeof(float);  // ~98 KB
    const int smem2 = (256 * WST + 128 * WST + 512 * 3 + 1536 * 3) * sizeof(float);  // 227328 B

    static bool attr_set = false;
    if (!attr_set) {
        cudaFuncSetAttribute(precompute_kernel,
                             cudaFuncAttributeMaxDynamicSharedMemorySize, smem1);
        cudaFuncSetAttribute(gru_kernel,
                             cudaFuncAttributeMaxDynamicSharedMemorySize, smem2);
        attr_set = true;
    }

    sort_all_kernel<<<1, NB>>>(seq_lens);
    precompute_kernel<<<NB, 256, smem1>>>(item_his, seq_lens, embedding,
                                          gate_kernel, gate_bias,
                                          cand_kernel, cand_bias);
    gru_kernel<<<NBLK, 512, smem2>>>(seq_lens, gate_kernel, cand_kernel, out);
}

// round 6
// speedup vs baseline: 3.1523x; 1.2523x over previous
#include <cuda_runtime.h>
#include <cstdint>

// Problem constants
#define NB   1024   // batch
#define NT   256    // time steps
#define ND   64     // embedding dim
#define NH   128    // hidden dim
#define N2H  256    // 2*H
#define RPB  4      // rows per gru block
#define NBLK (NB / RPB)
#define WST  132    // padded k-stride for transposed Whc (conflict-free LDS.128)
#define XST  12     // padded row-stride for transposed x stage

// Scratch (device globals; rewritten deterministically each launch)
__device__ float g_Xg[(size_t)NB * NT * N2H];  // 256 MB
__device__ float g_Xc[(size_t)NB * NT * NH];   // 128 MB
__device__ int   g_perm[NB];

// ---------------------------------------------------------------------------
// packed f32x2 helpers (sm_100+): ptxas won't emit FFMA2 from C++, so PTX.
// ---------------------------------------------------------------------------
__device__ __forceinline__ uint64_t dup2(float w) {
    uint64_t r; uint32_t wi = __float_as_uint(w);
    asm("mov.b64 %0, {%1, %1};" : "=l"(r) : "r"(wi));
    return r;
}
__device__ __forceinline__ void fma2(uint64_t& d, uint64_t a, uint64_t b) {
    asm("fma.rn.f32x2 %0, %1, %2, %0;" : "+l"(d) : "l"(a), "l"(b));
}
__device__ __forceinline__ uint64_t add2(uint64_t a, uint64_t b) {
    uint64_t r; asm("add.rn.f32x2 %0, %1, %2;" : "=l"(r) : "l"(a), "l"(b));
    return r;
}
__device__ __forceinline__ float2 unpk(uint64_t v) {
    uint32_t lo, hi;
    asm("mov.b64 {%0, %1}, %2;" : "=r"(lo), "=r"(hi) : "l"(v));
    return make_float2(__uint_as_float(lo), __uint_as_float(hi));
}

__device__ __forceinline__ float sigf(float x) {
    return __fdividef(1.f, 1.f + __expf(-x));
}
__device__ __forceinline__ float tanhfast(float x) {
    float e = __expf(2.f * x);          // inf for large x -> result 1
    return 1.f - __fdividef(2.f, e + 1.f);
}

// ---------------------------------------------------------------------------
// Single-launch counting sort of batch rows by seq_len, DESCENDING (LPT).
// ---------------------------------------------------------------------------
__global__ __launch_bounds__(NB, 1)
void sort_all_kernel(const int* __restrict__ lens) {
    __shared__ int hist[256];
    __shared__ int off[256];
    const int tid = threadIdx.x;
    if (tid < 256) hist[tid] = 0;
    __syncthreads();
    const int l = min(max(lens[tid], 0), 255);
    atomicAdd(&hist[l], 1);
    __syncthreads();
    if (tid == 0) {
        int run = 0;
        for (int i = 255; i >= 0; --i) { off[i] = run; run += hist[i]; }
    }
    __syncthreads();
    int p = atomicAdd(&off[l], 1);
    g_perm[p] = tid;
}

// ---------------------------------------------------------------------------
// Kernel 1: precompute Xg = x @ Wxg + gate_bias, Xc = x @ Wxc + cand_bias
// One block per batch row b; chunks of 8 timesteps; transposed x stage so the
// 8 rows are processed as 4 packed f32x2 pairs with one weight-dup per k.
// ---------------------------------------------------------------------------
__global__ __launch_bounds__(256, 2)
void precompute_kernel(const int* __restrict__ item_his,
                       const int* __restrict__ seq_lens,
                       const float* __restrict__ embedding,
                       const float* __restrict__ gate_kernel,
                       const float* __restrict__ gate_bias,
                       const float* __restrict__ cand_kernel,
                       const float* __restrict__ cand_bias) {
    extern __shared__ float sm[];
    float* Wxg = sm;                    // 64*256 = 16384
    float* Wxc = Wxg + 64 * N2H;        // 64*128 = 8192
    float* xsT = Wxc + 64 * NH;         // 64*XST = 768  (xsT[k*XST + r])

    const int tid = threadIdx.x;
    const int b   = blockIdx.x;
    const int len = seq_lens[b];

    for (int i = tid; i < (64 * N2H) / 4; i += 256)
        ((float4*)Wxg)[i] = ((const float4*)gate_kernel)[i];
    for (int i = tid; i < (64 * NH) / 4; i += 256)
        ((float4*)Wxc)[i] = ((const float4*)cand_kernel)[i];
    __syncthreads();

    if (len <= 0) return;

    const float gb = gate_bias[tid];
    const int   cc = tid & 127;
    const int   r0 = (tid >> 7) * 4;    // 0 or 4
    const float cb = cand_bias[cc];

    const int j = tid >> 5;          // gather row 0..7
    const int e = (tid & 31) * 2;    // gather k pair

    // prefetch chunk 0
    float2 v = make_float2(0.f, 0.f);
    if (j < len) {
        int idx = item_his[b * NT + j];
        v = *(const float2*)&embedding[(size_t)idx * ND + e];
    }

    for (int t0 = 0; t0 < len; t0 += 8) {
        xsT[(e + 0) * XST + j] = v.x;
        xsT[(e + 1) * XST + j] = v.y;
        __syncthreads();

        // prefetch next chunk (overlaps with compute below)
        {
            int t = t0 + 8 + j;
            v = make_float2(0.f, 0.f);
            if (t < len) {
                int idx = item_his[b * NT + t];
                v = *(const float2*)&embedding[(size_t)idx * ND + e];
            }
        }

        // ---- Xg: thread == gate column (0..255), rows packed as 4 pairs
        uint64_t a01 = 0, a23 = 0, a45 = 0, a67 = 0;
        #pragma unroll 8
        for (int k = 0; k < 64; k++) {
            uint64_t d = dup2(Wxg[k * N2H + tid]);
            ulonglong2 h03 = *(const ulonglong2*)&xsT[k * XST + 0];
            ulonglong2 h47 = *(const ulonglong2*)&xsT[k * XST + 4];
            fma2(a01, h03.x, d); fma2(a23, h03.y, d);
            fma2(a45, h47.x, d); fma2(a67, h47.y, d);
        }
        {
            float2 v01 = unpk(a01), v23 = unpk(a23), v45 = unpk(a45), v67 = unpk(a67);
            float accs[8] = {v01.x, v01.y, v23.x, v23.y, v45.x, v45.y, v67.x, v67.y};
            #pragma unroll
            for (int r = 0; r < 8; r++) {
                int t = t0 + r;
                if (t < len)
                    g_Xg[((size_t)b * NT + t) * N2H + tid] = accs[r] + gb;
            }
        }

        // ---- Xc: column = tid&127, rows r0..r0+3 packed as 2 pairs
        uint64_t b01 = 0, b23 = 0;
        #pragma unroll 8
        for (int k = 0; k < 64; k++) {
            uint64_t d = dup2(Wxc[k * NH + cc]);
            ulonglong2 hh = *(const ulonglong2*)&xsT[k * XST + r0];
            fma2(b01, hh.x, d); fma2(b23, hh.y, d);
        }
        {
            float2 v01 = unpk(b01), v23 = unpk(b23);
            float accs[4] = {v01.x, v01.y, v23.x, v23.y};
            #pragma unroll
            for (int r = 0; r < 4; r++) {
                int t = t0 + r0 + r;
                if (t < len)
                    g_Xc[((size_t)b * NT + t) * NH + cc] = accs[r] + cb;
            }
        }
        __syncthreads();
    }
}

// ---------------------------------------------------------------------------
// Kernel 2: recurrence. 256 blocks x 4 sorted rows, 512 threads.
// Phase-A weights (Whg) live in REGISTERS (64 scalars/thread, loaded once);
// phase-C weights (Whc) transposed in smem. Split-k x4, f32x2 FMA.
//   thread: sub = tid>>7 (k-quarter), cp = tid&127
// ---------------------------------------------------------------------------
__global__ __launch_bounds__(512, 1)
void gru_kernel(const int* __restrict__ seq_lens,
                const float* __restrict__ gate_kernel,
                const float* __restrict__ cand_kernel,
                float* __restrict__ out) {
    extern __shared__ float sm[];
    float* WcT  = sm;                    // 128*132 = 16896 floats
    float* hsT  = WcT + 128 * WST;       // 512  (hsT[k*4 + r])
    float* rhT  = hsT + 512;             // 512
    float* us   = rhT + 512;             // 512
    float* psA1 = us + 512;              // 3*128*4 = 1536 (r-gate partials)
    float* psA2 = psA1 + 1536;           // 1536 (u-gate partials)
    float* pcC  = psA2 + 1536;           // 1536 (cand partials)
    __shared__ int s_len[RPB];
    __shared__ int s_ob[RPB];
    __shared__ int s_maxlen;

    const int tid = threadIdx.x;
    const int sub = tid >> 7;   // k-quarter 0..3
    const int cp  = tid & 127;  // column (A: cp & cp+128; C: cp)
    const int k0  = sub * 32;

    // Transposed Whc into smem: WcT[c*WST+k] = Whc[k][c]
    {
        const float4* Wc4 = (const float4*)(cand_kernel + 64 * NH);   // [k][c]
        for (int i = tid; i < (NH * NH) / 4; i += 512) {
            int k = i >> 5, c4 = (i & 31) * 4;
            float4 w = Wc4[i];
            WcT[(c4 + 0) * WST + k] = w.x;
            WcT[(c4 + 1) * WST + k] = w.y;
            WcT[(c4 + 2) * WST + k] = w.z;
            WcT[(c4 + 3) * WST + k] = w.w;
        }
    }
    for (int i = tid; i < RPB * NH; i += 512) hsT[i] = 0.f;
    if (tid < RPB) {
        int ob = g_perm[blockIdx.x * RPB + tid];
        s_ob[tid] = ob;
        s_len[tid] = seq_lens[ob];
    }

    // Phase-A weights into registers: columns {cp, cp+128}, k in [k0,k0+32)
    float wA0[32], wA1[32];
    {
        const float* Wg = gate_kernel + 64 * N2H;   // [k][c] rows 64..191
        #pragma unroll
        for (int i = 0; i < 32; i++) {
            wA0[i] = __ldg(&Wg[(k0 + i) * N2H + cp]);
            wA1[i] = __ldg(&Wg[(k0 + i) * N2H + cp + 128]);
        }
    }

    __syncthreads();
    if (tid == 0) {
        int m = 0;
        #pragma unroll
        for (int jj = 0; jj < RPB; jj++) m = max(m, s_len[jj]);
        s_maxlen = m;
    }
    __syncthreads();
    const int maxlen = s_maxlen;

    int ob0 = s_ob[0], ob1 = s_ob[1], ob2 = s_ob[2], ob3 = s_ob[3];
    int ln0 = s_len[0], ln1 = s_len[1], ln2 = s_len[2], ln3 = s_len[3];

    const float4*     wC = (const float4*)&WcT[cp * WST + k0];
    const ulonglong2* hp = (const ulonglong2*)&hsT[k0 * 4];
    const ulonglong2* rp = (const ulonglong2*)&rhT[k0 * 4];

    for (int t = 0; t < maxlen; t++) {
        // Prefetch input contributions (sub==0 threads; consumed after barrier)
        float xgr[4], xgu[4], xcv[4];
        if (sub == 0) {
            size_t og0 = ((size_t)(ob0 * NT + t)) * N2H + cp;
            size_t og1 = ((size_t)(ob1 * NT + t)) * N2H + cp;
            size_t og2 = ((size_t)(ob2 * NT + t)) * N2H + cp;
            size_t og3 = ((size_t)(ob3 * NT + t)) * N2H + cp;
            xgr[0] = __ldg(&g_Xg[og0]); xgu[0] = __ldg(&g_Xg[og0 + NH]);
            xgr[1] = __ldg(&g_Xg[og1]); xgu[1] = __ldg(&g_Xg[og1 + NH]);
            xgr[2] = __ldg(&g_Xg[og2]); xgu[2] = __ldg(&g_Xg[og2 + NH]);
            xgr[3] = __ldg(&g_Xg[og3]); xgu[3] = __ldg(&g_Xg[og3 + NH]);
            xcv[0] = __ldg(&g_Xc[((size_t)(ob0 * NT + t)) * NH + cp]);
            xcv[1] = __ldg(&g_Xc[((size_t)(ob1 * NT + t)) * NH + cp]);
            xcv[2] = __ldg(&g_Xc[((size_t)(ob2 * NT + t)) * NH + cp]);
            xcv[3] = __ldg(&g_Xc[((size_t)(ob3 * NT + t)) * NH + cp]);
        }

        // ---- Phase A main: partial h @ Whg, weights from REGISTERS
        uint64_t a00 = 0, a01 = 0, a10 = 0, a11 = 0;
        #pragma unroll
        for (int i = 0; i < 32; i++) {
            ulonglong2 hk = hp[i];
            uint64_t d = dup2(wA0[i]);
            uint64_t e = dup2(wA1[i]);
            fma2(a00, hk.x, d); fma2(a01, hk.y, d);
            fma2(a10, hk.x, e); fma2(a11, hk.y, e);
        }
        if (sub != 0) {
            ulonglong2 v1; v1.x = a00; v1.y = a01;
            ulonglong2 v2; v2.x = a10; v2.y = a11;
            *(ulonglong2*)&psA1[((sub - 1) * 128 + cp) * 4] = v1;
            *(ulonglong2*)&psA2[((sub - 1) * 128 + cp) * 4] = v2;
        }
        __syncthreads();

        // ---- Phase A epilogue (sub==0): reduce, sigmoid, build rhT & us
        if (sub == 0) {
            #pragma unroll
            for (int jj = 0; jj < 3; jj++) {
                ulonglong2 v1 = *(const ulonglong2*)&psA1[(jj * 128 + cp) * 4];
                ulonglong2 v2 = *(const ulonglong2*)&psA2[(jj * 128 + cp) * 4];
                a00 = add2(a00, v1.x); a01 = add2(a01, v1.y);
                a10 = add2(a10, v2.x); a11 = add2(a11, v2.y);
            }
            float2 r01 = unpk(a00), r23 = unpk(a01);
            float2 u01 = unpk(a10), u23 = unpk(a11);
            float rg[4] = {r01.x, r01.y, r23.x, r23.y};
            float ug[4] = {u01.x, u01.y, u23.x, u23.y};
            float4 hv = *(const float4*)&hsT[cp * 4];
            float hh[4] = {hv.x, hv.y, hv.z, hv.w};
            float rh4[4], uu4[4];
            #pragma unroll
            for (int r = 0; r < 4; r++) {
                float gr = sigf(rg[r] + xgr[r]);
                float gu = sigf(ug[r] + xgu[r]);
                rh4[r] = gr * hh[r];
                uu4[r] = gu;
            }
            *(float4*)&rhT[cp * 4] = make_float4(rh4[0], rh4[1], rh4[2], rh4[3]);
            *(float4*)&us[cp * 4]  = make_float4(uu4[0], uu4[1], uu4[2], uu4[3]);
        }
        __syncthreads();

        // ---- Phase C main: partial rh @ Whc, weights from smem
        uint64_t b0 = 0, b1 = 0;
        #pragma unroll
        for (int i = 0; i < 8; i++) {
            float4 w = wC[i];
            ulonglong2 hA = rp[4 * i + 0];
            ulonglong2 hB = rp[4 * i + 1];
            ulonglong2 hC = rp[4 * i + 2];
            ulonglong2 hD = rp[4 * i + 3];
            uint64_t d;
            d = dup2(w.x); fma2(b0, hA.x, d); fma2(b1, hA.y, d);
            d = dup2(w.y); fma2(b0, hB.x, d); fma2(b1, hB.y, d);
            d = dup2(w.z); fma2(b0, hC.x, d); fma2(b1, hC.y, d);
            d = dup2(w.w); fma2(b0, hD.x, d); fma2(b1, hD.y, d);
        }
        if (sub != 0) {
            ulonglong2 v; v.x = b0; v.y = b1;
            *(ulonglong2*)&pcC[((sub - 1) * 128 + cp) * 4] = v;
        }
        __syncthreads();

        // ---- Phase C epilogue (sub==0): reduce, tanh, masked h update
        if (sub == 0) {
            #pragma unroll
            for (int jj = 0; jj < 3; jj++) {
                ulonglong2 v = *(const ulonglong2*)&pcC[(jj * 128 + cp) * 4];
                b0 = add2(b0, v.x); b1 = add2(b1, v.y);
            }
            float2 c01 = unpk(b0), c23 = unpk(b1);
            float cs[4] = {c01.x, c01.y, c23.x, c23.y};
            float4 hv = *(const float4*)&hsT[cp * 4];
            float4 uv = *(const float4*)&us[cp * 4];
            float hh[4] = {hv.x, hv.y, hv.z, hv.w};
            float uu[4] = {uv.x, uv.y, uv.z, uv.w};
            int lns[4] = {ln0, ln1, ln2, ln3};
            float hn[4];
            #pragma unroll
            for (int r = 0; r < 4; r++) {
                float cnd = tanhfast(cs[r] + xcv[r]);
                float h2  = uu[r] * hh[r] + (1.f - uu[r]) * cnd;
                hn[r] = (t < lns[r]) ? h2 : hh[r];
            }
            *(float4*)&hsT[cp * 4] = make_float4(hn[0], hn[1], hn[2], hn[3]);
        }
        __syncthreads();
    }

    // Scatter final h to original batch positions: hsT[k*4+r] = h[r][k]
    for (int i = tid; i < RPB * NH; i += 512) {
        int k = i >> 2, r = i & 3;
        out[s_ob[r] * NH + k] = hsT[i];
    }
}

// ---------------------------------------------------------------------------
extern "C" void kernel_launch(void* const* d_in, const int* in_sizes, int n_in,
                              void* d_out, int out_size) {
    const int*   item_his    = (const int*)d_in[0];
    const int*   seq_lens    = (const int*)d_in[1];
    const float* embedding   = (const float*)d_in[2];
    const float* gate_kernel = (const float*)d_in[3];
    const float* gate_bias   = (const float*)d_in[4];
    const float* cand_kernel = (const float*)d_in[5];
    const float* cand_bias   = (const float*)d_in[6];
    float* out = (float*)d_out;

    const int smem1 = (64 * N2H + 64 * NH + 64 * XST) * sizeof(float);            // ~99 KB
    const int smem2 = (128 * WST + 512 * 3 + 1536 * 3) * sizeof(float);           // ~90 KB

    static bool attr_set = false;
    if (!attr_set) {
        cudaFuncSetAttribute(precompute_kernel,
                             cudaFuncAttributeMaxDynamicSharedMemorySize, smem1);
        cudaFuncSetAttribute(gru_kernel,
                             cudaFuncAttributeMaxDynamicSharedMemorySize, smem2);
        attr_set = true;
    }

    sort_all_kernel<<<1, NB>>>(seq_lens);
    precompute_kernel<<<NB, 256, smem1>>>(item_his, seq_lens, embedding,
                                          gate_kernel, gate_bias,
                                          cand_kernel, cand_bias);
    gru_kernel<<<NBLK, 512, smem2>>>(seq_lens, gate_kernel, cand_kernel, out);
}

// round 11
// speedup vs baseline: 3.1837x; 1.0100x over previous
#include <cuda_runtime.h>
#include <cstdint>

// Problem constants
#define NB   1024   // batch
#define NT   256    // time steps
#define ND   64     // embedding dim
#define NH   128    // hidden dim
#define N2H  256    // 2*H
#define RPB  4      // rows per gru block
#define NBLK (NB / RPB)
#define WST  133    // padded k-stride for transposed Whc (bank stride 5 -> conflict-free scalar)
#define XST  12     // padded row-stride for transposed x stage

// Scratch (device globals; rewritten deterministically each launch)
__device__ float g_Xg[(size_t)NB * NT * N2H];  // 256 MB
__device__ float g_Xc[(size_t)NB * NT * NH];   // 128 MB
__device__ int   g_perm[NB];

// ---------------------------------------------------------------------------
// packed f32x2 helpers (sm_100+): ptxas won't emit FFMA2 from C++, so PTX.
// ---------------------------------------------------------------------------
__device__ __forceinline__ uint64_t dup2(float w) {
    uint64_t r; uint32_t wi = __float_as_uint(w);
    asm("mov.b64 %0, {%1, %1};" : "=l"(r) : "r"(wi));
    return r;
}
__device__ __forceinline__ void fma2(uint64_t& d, uint64_t a, uint64_t b) {
    asm("fma.rn.f32x2 %0, %1, %2, %0;" : "+l"(d) : "l"(a), "l"(b));
}
__device__ __forceinline__ uint64_t add2(uint64_t a, uint64_t b) {
    uint64_t r; asm("add.rn.f32x2 %0, %1, %2;" : "=l"(r) : "l"(a), "l"(b));
    return r;
}
__device__ __forceinline__ float2 unpk(uint64_t v) {
    uint32_t lo, hi;
    asm("mov.b64 {%0, %1}, %2;" : "=r"(lo), "=r"(hi) : "l"(v));
    return make_float2(__uint_as_float(lo), __uint_as_float(hi));
}

__device__ __forceinline__ float sigf(float x) {
    return __fdividef(1.f, 1.f + __expf(-x));
}
__device__ __forceinline__ float tanhfast(float x) {
    float e = __expf(2.f * x);          // inf for large x -> result 1
    return 1.f - __fdividef(2.f, e + 1.f);
}

// ---------------------------------------------------------------------------
// Single-launch counting sort of batch rows by seq_len, DESCENDING (LPT).
// ---------------------------------------------------------------------------
__global__ __launch_bounds__(NB, 1)
void sort_all_kernel(const int* __restrict__ lens) {
    __shared__ int hist[256];
    __shared__ int off[256];
    const int tid = threadIdx.x;
    if (tid < 256) hist[tid] = 0;
    __syncthreads();
    const int l = min(max(lens[tid], 0), 255);
    atomicAdd(&hist[l], 1);
    __syncthreads();
    if (tid == 0) {
        int run = 0;
        for (int i = 255; i >= 0; --i) { off[i] = run; run += hist[i]; }
    }
    __syncthreads();
    int p = atomicAdd(&off[l], 1);
    g_perm[p] = tid;
}

// ---------------------------------------------------------------------------
// Kernel 1: precompute Xg = x @ Wxg + gate_bias, Xc = x @ Wxc + cand_bias
// One block per batch row b; chunks of 8 timesteps; transposed x stage so the
// 8 rows are processed as 4 packed f32x2 pairs with one weight-dup per k.
// ---------------------------------------------------------------------------
__global__ __launch_bounds__(256, 2)
void precompute_kernel(const int* __restrict__ item_his,
                       const int* __restrict__ seq_lens,
                       const float* __restrict__ embedding,
                       const float* __restrict__ gate_kernel,
                       const float* __restrict__ gate_bias,
                       const float* __restrict__ cand_kernel,
                       const float* __restrict__ cand_bias) {
    extern __shared__ float sm[];
    float* Wxg = sm;                    // 64*256 = 16384
    float* Wxc = Wxg + 64 * N2H;        // 64*128 = 8192
    float* xsT = Wxc + 64 * NH;         // 64*XST = 768  (xsT[k*XST + r])

    const int tid = threadIdx.x;
    const int b   = blockIdx.x;
    const int len = seq_lens[b];

    for (int i = tid; i < (64 * N2H) / 4; i += 256)
        ((float4*)Wxg)[i] = ((const float4*)gate_kernel)[i];
    for (int i = tid; i < (64 * NH) / 4; i += 256)
        ((float4*)Wxc)[i] = ((const float4*)cand_kernel)[i];
    __syncthreads();

    if (len <= 0) return;

    const float gb = gate_bias[tid];
    const int   cc = tid & 127;
    const int   r0 = (tid >> 7) * 4;    // 0 or 4
    const float cb = cand_bias[cc];

    const int j = tid >> 5;          // gather row 0..7
    const int e = (tid & 31) * 2;    // gather k pair

    // prefetch chunk 0
    float2 v = make_float2(0.f, 0.f);
    if (j < len) {
        int idx = item_his[b * NT + j];
        v = *(const float2*)&embedding[(size_t)idx * ND + e];
    }

    for (int t0 = 0; t0 < len; t0 += 8) {
        xsT[(e + 0) * XST + j] = v.x;
        xsT[(e + 1) * XST + j] = v.y;
        __syncthreads();

        // prefetch next chunk (overlaps with compute below)
        {
            int t = t0 + 8 + j;
            v = make_float2(0.f, 0.f);
            if (t < len) {
                int idx = item_his[b * NT + t];
                v = *(const float2*)&embedding[(size_t)idx * ND + e];
            }
        }

        // ---- Xg: thread == gate column (0..255), rows packed as 4 pairs
        uint64_t a01 = 0, a23 = 0, a45 = 0, a67 = 0;
        #pragma unroll 8
        for (int k = 0; k < 64; k++) {
            uint64_t d = dup2(Wxg[k * N2H + tid]);
            ulonglong2 h03 = *(const ulonglong2*)&xsT[k * XST + 0];
            ulonglong2 h47 = *(const ulonglong2*)&xsT[k * XST + 4];
            fma2(a01, h03.x, d); fma2(a23, h03.y, d);
            fma2(a45, h47.x, d); fma2(a67, h47.y, d);
        }
        {
            float2 v01 = unpk(a01), v23 = unpk(a23), v45 = unpk(a45), v67 = unpk(a67);
            float accs[8] = {v01.x, v01.y, v23.x, v23.y, v45.x, v45.y, v67.x, v67.y};
            #pragma unroll
            for (int r = 0; r < 8; r++) {
                int t = t0 + r;
                if (t < len)
                    g_Xg[((size_t)b * NT + t) * N2H + tid] = accs[r] + gb;
            }
        }

        // ---- Xc: column = tid&127, rows r0..r0+3 packed as 2 pairs
        uint64_t b01 = 0, b23 = 0;
        #pragma unroll 8
        for (int k = 0; k < 64; k++) {
            uint64_t d = dup2(Wxc[k * NH + cc]);
            ulonglong2 hh = *(const ulonglong2*)&xsT[k * XST + r0];
            fma2(b01, hh.x, d); fma2(b23, hh.y, d);
        }
        {
            float2 v01 = unpk(b01), v23 = unpk(b23);
            float accs[4] = {v01.x, v01.y, v23.x, v23.y};
            #pragma unroll
            for (int r = 0; r < 4; r++) {
                int t = t0 + r0 + r;
                if (t < len)
                    g_Xc[((size_t)b * NT + t) * NH + cc] = accs[r] + cb;
            }
        }
        __syncthreads();
    }
}

// ---------------------------------------------------------------------------
// Kernel 2: recurrence. 256 blocks x 4 sorted rows, 1024 threads (32 warps).
// Phase A: thread = (col pair {c2, c2+128}, k-eighth), weights in registers.
// Phase C: thread = (col pair {cc2, cc2+64}, k-sixteenth), weights from smem.
// Epilogues spread over 512 / 256 threads. All f32x2 packed math.
// ---------------------------------------------------------------------------
__global__ __launch_bounds__(1024, 1)
void gru_kernel(const int* __restrict__ seq_lens,
                const float* __restrict__ gate_kernel,
                const float* __restrict__ cand_kernel,
                float* __restrict__ out) {
    extern __shared__ float sm[];
    float* WcT   = sm;                    // 128*133 = 17024 floats
    float* hsT   = WcT + 128 * WST;       // 512  (hsT[k*4 + r])
    float* rhT   = hsT + 512;             // 512
    float* us    = rhT + 512;             // 512
    float* psA_r = us + 512;              // 8 subs * 128 cols * 4 = 4096
    float* psA_u = psA_r + 4096;          // 4096
    float* pcC0  = psA_u + 4096;          // 16 subs * 64 cols * 4 = 4096
    float* pcC1  = pcC0 + 4096;           // 4096
    __shared__ int s_len[RPB];
    __shared__ int s_ob[RPB];
    __shared__ int s_maxlen;

    const int tid = threadIdx.x;

    // Transposed Whc into smem: WcT[c*WST+k] = Whc[k][c]
    {
        const float4* Wc4 = (const float4*)(cand_kernel + 64 * NH);   // [k][c]
        for (int i = tid; i < (NH * NH) / 4; i += 1024) {
            int k = i >> 5, c4 = (i & 31) * 4;
            float4 w = Wc4[i];
            WcT[(c4 + 0) * WST + k] = w.x;
            WcT[(c4 + 1) * WST + k] = w.y;
            WcT[(c4 + 2) * WST + k] = w.z;
            WcT[(c4 + 3) * WST + k] = w.w;
        }
    }
    for (int i = tid; i < RPB * NH; i += 1024) hsT[i] = 0.f;
    if (tid < RPB) {
        int ob = g_perm[blockIdx.x * RPB + tid];
        s_ob[tid] = ob;
        s_len[tid] = seq_lens[ob];
    }

    // ---- Phase A mapping & register weights
    const int c2   = tid & 127;      // column pair {c2, c2+128}
    const int subA = tid >> 7;       // k-eighth 0..7
    const int k0a  = subA * 16;
    float wA0[16], wA1[16];
    {
        const float* Wg = gate_kernel + 64 * N2H;   // [k][c] rows 64..191
        #pragma unroll
        for (int i = 0; i < 16; i++) {
            wA0[i] = __ldg(&Wg[(k0a + i) * N2H + c2]);
            wA1[i] = __ldg(&Wg[(k0a + i) * N2H + c2 + 128]);
        }
    }

    // ---- Phase C mapping
    const int cc2  = tid & 63;       // column pair {cc2, cc2+64}
    const int subC = tid >> 6;       // k-sixteenth 0..15
    const int k0c  = subC * 8;
    const float* wcp0 = &WcT[cc2 * WST + k0c];
    const float* wcp1 = &WcT[(cc2 + 64) * WST + k0c];

    __syncthreads();
    if (tid == 0) {
        int m = 0;
        #pragma unroll
        for (int jj = 0; jj < RPB; jj++) m = max(m, s_len[jj]);
        s_maxlen = m;
    }
    __syncthreads();
    const int maxlen = s_maxlen;

    // ---- Epilogue-A role (tid < 512): output (col cA 0..255, row-pair pA)
    int egA0 = 0, egA1 = 0;
    const int cA = tid & 255, pA = (tid >> 8) & 1;
    const int pA2 = 2 * pA;
    if (tid < 512) {
        egA0 = s_ob[pA2]     * NT * N2H + cA;
        egA1 = s_ob[pA2 + 1] * NT * N2H + cA;
    }
    // ---- Epilogue-C role (tid < 256): output (col cE 0..127, row-pair pC)
    int egC0 = 0, egC1 = 0, lnC0 = 0, lnC1 = 0;
    const int cE = tid & 127, pC = (tid >> 7) & 1;
    const int pC2 = 2 * pC;
    if (tid < 256) {
        egC0 = s_ob[pC2]     * NT * NH + cE;
        egC1 = s_ob[pC2 + 1] * NT * NH + cE;
        lnC0 = s_len[pC2];
        lnC1 = s_len[pC2 + 1];
    }

    for (int t = 0; t < maxlen; t++) {
        // Distributed prefetch of input contributions
        float xg0 = 0.f, xg1 = 0.f, xc0 = 0.f, xc1 = 0.f;
        if (tid < 512) {
            xg0 = __ldg(&g_Xg[(size_t)egA0 + (size_t)t * N2H]);
            xg1 = __ldg(&g_Xg[(size_t)egA1 + (size_t)t * N2H]);
        }
        if (tid < 256) {
            xc0 = __ldg(&g_Xc[(size_t)egC0 + (size_t)t * NH]);
            xc1 = __ldg(&g_Xc[(size_t)egC1 + (size_t)t * NH]);
        }

        // ---- Phase A main: partial h @ Whg (k in [k0a,k0a+16), cols c2 & c2+128)
        uint64_t a00 = 0, a01 = 0, a10 = 0, a11 = 0;
        #pragma unroll
        for (int i = 0; i < 16; i++) {
            ulonglong2 hk = *(const ulonglong2*)&hsT[(k0a + i) * 4];
            uint64_t d0 = dup2(wA0[i]);
            uint64_t d1 = dup2(wA1[i]);
            fma2(a00, hk.x, d0); fma2(a01, hk.y, d0);
            fma2(a10, hk.x, d1); fma2(a11, hk.y, d1);
        }
        {
            ulonglong2 v1; v1.x = a00; v1.y = a01;
            ulonglong2 v2; v2.x = a10; v2.y = a11;
            ((ulonglong2*)psA_r)[subA * 128 + c2] = v1;
            ((ulonglong2*)psA_u)[subA * 128 + c2] = v2;
        }
        __syncthreads();

        // ---- Phase A epilogue (tid < 512): reduce 8 partials, sigmoid, rh/us
        if (tid < 512) {
            const uint64_t* pp = (const uint64_t*)(cA < 128 ? psA_r : psA_u);
            const int cl = cA & 127;
            uint64_t s = pp[(0 * 128 + cl) * 2 + pA];
            #pragma unroll
            for (int ss = 1; ss < 8; ss++)
                s = add2(s, pp[(ss * 128 + cl) * 2 + pA]);
            float2 v = unpk(s);
            float g0 = sigf(v.x + xg0);
            float g1 = sigf(v.y + xg1);
            if (cA < 128) {
                float2 hv = *(const float2*)&hsT[cA * 4 + pA2];
                float2 rv; rv.x = g0 * hv.x; rv.y = g1 * hv.y;
                *(float2*)&rhT[cA * 4 + pA2] = rv;
            } else {
                float2 uv; uv.x = g0; uv.y = g1;
                *(float2*)&us[(cA - 128) * 4 + pA2] = uv;
            }
        }
        __syncthreads();

        // ---- Phase C main: partial rh @ Whc (k in [k0c,k0c+8), cols cc2 & cc2+64)
        uint64_t b00 = 0, b01 = 0, b10 = 0, b11 = 0;
        #pragma unroll
        for (int jv = 0; jv < 8; jv++) {
            ulonglong2 hk = *(const ulonglong2*)&rhT[(k0c + jv) * 4];
            uint64_t d0 = dup2(wcp0[jv]);
            uint64_t d1 = dup2(wcp1[jv]);
            fma2(b00, hk.x, d0); fma2(b01, hk.y, d0);
            fma2(b10, hk.x, d1); fma2(b11, hk.y, d1);
        }
        {
            ulonglong2 v1; v1.x = b00; v1.y = b01;
            ulonglong2 v2; v2.x = b10; v2.y = b11;
            ((ulonglong2*)pcC0)[subC * 64 + cc2] = v1;
            ((ulonglong2*)pcC1)[subC * 64 + cc2] = v2;
        }
        __syncthreads();

        // ---- Phase C epilogue (tid < 256): reduce 16 partials, tanh, h update
        if (tid < 256) {
            const uint64_t* pp = (const uint64_t*)(cE < 64 ? pcC0 : pcC1);
            const int cl = cE & 63;
            uint64_t s = pp[(0 * 64 + cl) * 2 + pC];
            #pragma unroll
            for (int ss = 1; ss < 16; ss++)
                s = add2(s, pp[(ss * 64 + cl) * 2 + pC]);
            float2 v = unpk(s);
            float cn0 = tanhfast(v.x + xc0);
            float cn1 = tanhfast(v.y + xc1);
            float2 uv = *(const float2*)&us[cE * 4 + pC2];
            float2 hv = *(const float2*)&hsT[cE * 4 + pC2];
            float h0 = uv.x * hv.x + (1.f - uv.x) * cn0;
            float h1 = uv.y * hv.y + (1.f - uv.y) * cn1;
            float2 hn;
            hn.x = (t < lnC0) ? h0 : hv.x;
            hn.y = (t < lnC1) ? h1 : hv.y;
            *(float2*)&hsT[cE * 4 + pC2] = hn;
        }
        __syncthreads();
    }

    // Scatter final h to original batch positions: hsT[k*4+r] = h[r][k]
    for (int i = tid; i < RPB * NH; i += 1024) {
        int k = i >> 2, r = i & 3;
        out[s_ob[r] * NH + k] = hsT[i];
    }
}

// ---------------------------------------------------------------------------
extern "C" void kernel_launch(void* const* d_in, const int* in_sizes, int n_in,
                              void* d_out, int out_size) {
    const int*   item_his    = (const int*)d_in[0];
    const int*   seq_lens    = (const int*)d_in[1];
    const float* embedding   = (const float*)d_in[2];
    const float* gate_kernel = (const float*)d_in[3];
    const float* gate_bias   = (const float*)d_in[4];
    const float* cand_kernel = (const float*)d_in[5];
    const float* cand_bias   = (const float*)d_in[6];
    float* out = (float*)d_out;

    const int smem1 = (64 * N2H + 64 * NH + 64 * XST) * sizeof(float);          // ~99 KB
    const int smem2 = (128 * WST + 512 * 3 + 4096 * 4) * sizeof(float);         // ~139 KB

    static bool attr_set = false;
    if (!attr_set) {
        cudaFuncSetAttribute(precompute_kernel,
                             cudaFuncAttributeMaxDynamicSharedMemorySize, smem1);
        cudaFuncSetAttribute(gru_kernel,
                             cudaFuncAttributeMaxDynamicSharedMemorySize, smem2);
        attr_set = true;
    }

    sort_all_kernel<<<1, NB>>>(seq_lens);
    precompute_kernel<<<NB, 256, smem1>>>(item_his, seq_lens, embedding,
                                          gate_kernel, gate_bias,
                                          cand_kernel, cand_bias);
    gru_kernel<<<NBLK, 1024, smem2>>>(seq_lens, gate_kernel, cand_kernel, out);
}